// round 17
// baseline (speedup 1.0000x reference)
#include <cuda_runtime.h>
#include <cuda_bf16.h>
#include <math.h>

// Problem constants
#define N_EMBED   512
#define EMBED_DIM 64
#define K_SPARSE  4
#define NSIG      16384           // 16 * 32 * 32
#define ZQ_ELEMS  1048576         // 16 * 64 * 32 * 32
#define N_BINS    33
#define WARPS_PER_BLOCK 8
#define OMP_GROUPS (NSIG / WARPS_PER_BLOCK)   // 2048 groups of 8 signals
#define HBAR_BLOCKS 1024
#define MID_TILES  (HBAR_BLOCKS + N_EMBED / 2)   // 1280
#define SMEM_BYTES 49152                         // 12288 floats

typedef unsigned long long ull;

// Scratch (device globals: allocations are forbidden)
__device__ float g_Dn [EMBED_DIM * N_EMBED];     // normalized dict, dim-major [64][512]
__device__ float g_DnT[N_EMBED * EMBED_DIM];     // normalized dict, atom-major [512][64]
__device__ float g_G  [N_EMBED * N_EMBED];       // Gram matrix [512][512]
__device__ float g_hbar[(size_t)NSIG * N_EMBED]; // correlations [16384][512] (32 MB)
__device__ float g_part[OMP_GROUPS];             // per-group loss partials
__device__ int            g_bcount;              // barrier arrival counter
__device__ volatile unsigned g_bgen;             // barrier generation

__device__ __forceinline__ unsigned redux_max_u32(unsigned v) {
    unsigned r;
    asm("redux.sync.max.u32 %0, %1, 0xffffffff;" : "=r"(r) : "r"(v));
    return r;
}
__device__ __forceinline__ unsigned redux_min_u32(unsigned v) {
    unsigned r;
    asm("redux.sync.min.u32 %0, %1, 0xffffffff;" : "=r"(r) : "r"(v));
    return r;
}
#define FMA2(acc, a, b) \
    asm("fma.rn.f32x2 %0, %1, %2, %0;" : "+l"(acc) : "l"(a), "l"(b))
__device__ __forceinline__ ull pack2(float v) {
    ull r; unsigned u = __float_as_uint(v);
    asm("mov.b64 %0, {%1, %1};" : "=l"(r) : "r"(u));
    return r;
}

// Software grid barrier: every block resident (grid = occ * numSMs), so
// spinning is safe. Two-phase: arrive-count + generation flip.
__device__ __forceinline__ void grid_sync(int nblocks) {
    __syncthreads();
    if (threadIdx.x == 0) {
        __threadfence();
        unsigned gen = g_bgen;
        if (atomicAdd(&g_bcount, 1) == nblocks - 1) {
            g_bcount = 0;
            __threadfence();
            g_bgen = gen + 1;
        } else {
            while (g_bgen == gen) __nanosleep(32);
        }
        __threadfence();
    }
    __syncthreads();
}

// ---------------------------------------------------------------------------
// Persistent megakernel: norm -> (hbar GEMM + gram) -> OMP -> loss reduce.
__global__ void __launch_bounds__(256, 3) k_mega(const float* __restrict__ z_e,
                                                 const float* __restrict__ dict,
                                                 float* __restrict__ out,
                                                 int nblocks) {
    extern __shared__ float sm[];                       // 12288 floats (48 KB)
    __shared__ int   sh_sup[WARPS_PER_BLOCK][K_SPARSE];
    __shared__ float sh_cq [WARPS_PER_BLOCK][K_SPARSE];
    __shared__ float warp_loss[WARPS_PER_BLOCK];

    int tid  = threadIdx.x;
    int wid  = tid >> 5;
    int lane = tid & 31;

    // ======== Phase 1: dictionary normalization (warp per atom) ========
    {
        int n = blockIdx.x * WARPS_PER_BLOCK + wid;     // atom
        if (n < N_EMBED) {
            int m0 = lane * 2;
            float v0 = dict[m0 * N_EMBED + n];
            float v1 = dict[(m0 + 1) * N_EMBED + n];
            float ss = fmaf(v0, v0, v1 * v1);
            #pragma unroll
            for (int off = 16; off; off >>= 1)
                ss += __shfl_xor_sync(0xffffffffu, ss, off);
            float nr = fmaxf(sqrtf(ss), 1e-10f);
            float dn0 = v0 / nr;
            float dn1 = v1 / nr;
            g_Dn [m0 * N_EMBED + n]       = dn0;
            g_Dn [(m0 + 1) * N_EMBED + n] = dn1;
            *(float2*)(g_DnT + n * EMBED_DIM + m0) = make_float2(dn0, dn1);
        }
    }
    grid_sync(nblocks);

    // ======== Phase 2: h_bar tiles + Gram rows (grid-stride) ========
    for (int blk = blockIdx.x; blk < MID_TILES; blk += nblocks) {
        __syncthreads();                                // smem reuse fence
        if (blk < HBAR_BLOCKS) {
            // h_bar = Dn^T X. Tile: 64 signals x 128 atoms, K=64.
            float* Xs = sm;                             // [64][64]
            float* Ds = sm + EMBED_DIM * 64;            // [64][128]

            int bsig  = (blk >> 2) << 6;
            int batom = (blk & 3) << 7;
            int b   = bsig >> 10;
            int hw0 = bsig & 1023;

            {
                const float4* src = (const float4*)(z_e + b * 65536 + hw0);
                float4* dst = (float4*)Xs;
                #pragma unroll
                for (int r = 0; r < 4; ++r) {
                    int idx = tid + r * 256;
                    int m = idx >> 4, j4 = idx & 15;
                    dst[idx] = src[m * 256 + j4];
                }
            }
            {
                const float4* src = (const float4*)(g_Dn + batom);
                float4* dst = (float4*)Ds;
                #pragma unroll
                for (int r = 0; r < 8; ++r) {
                    int idx = tid + r * 256;
                    int m = idx >> 5, a4 = idx & 31;
                    dst[idx] = src[m * 128 + a4];
                }
            }
            __syncthreads();

            int tx = tid & 15, ty = tid >> 4;
            ull acc[4][4];
            #pragma unroll
            for (int i = 0; i < 4; ++i)
                #pragma unroll
                for (int j = 0; j < 4; ++j) acc[i][j] = 0ull;

            #pragma unroll 4
            for (int m = 0; m < EMBED_DIM; ++m) {
                float4 xv = *(const float4*)(Xs + m * 64 + ty * 4);
                ull xx[4] = {pack2(xv.x), pack2(xv.y), pack2(xv.z), pack2(xv.w)};
                const ull* Dp = (const ull*)(Ds + m * 128) + tx;
                ull dv[4];
                #pragma unroll
                for (int j = 0; j < 4; ++j) dv[j] = Dp[16 * j];
                #pragma unroll
                for (int i = 0; i < 4; ++i)
                    #pragma unroll
                    for (int j = 0; j < 4; ++j)
                        FMA2(acc[i][j], xx[i], dv[j]);
            }

            #pragma unroll
            for (int i = 0; i < 4; ++i) {
                int sig = bsig + ty * 4 + i;
                ull* row = (ull*)(g_hbar + (size_t)sig * N_EMBED + batom) + tx;
                #pragma unroll
                for (int j = 0; j < 4; ++j) row[16 * j] = acc[i][j];
            }
        } else {
            // Gram rows: 2 rows per tile, 128 threads per row.
            float* di = sm;                             // [2][64]
            int i0 = (blk - HBAR_BLOCKS) * 2;
            if (tid < 2 * EMBED_DIM)
                di[(tid >> 6) * EMBED_DIM + (tid & 63)] =
                    g_DnT[(i0 + (tid >> 6)) * EMBED_DIM + (tid & 63)];
            __syncthreads();
            int half = tid >> 7;
            int col  = tid & 127;
            int i = i0 + half;
            float acc[4] = {0.f, 0.f, 0.f, 0.f};
            #pragma unroll 8
            for (int m = 0; m < EMBED_DIM; ++m) {
                float dm = di[half * EMBED_DIM + m];
                const float* row = g_Dn + m * N_EMBED + col;
                #pragma unroll
                for (int t = 0; t < 4; ++t)
                    acc[t] = fmaf(dm, row[t * 128], acc[t]);
            }
            #pragma unroll
            for (int t = 0; t < 4; ++t)
                g_G[i * N_EMBED + col + t * 128] = acc[t];
        }
    }
    grid_sync(nblocks);

    // ======== Phase 3: OMP (grid-stride over 2048 signal groups) ========
    for (int grp = blockIdx.x; grp < OMP_GROUPS; grp += nblocks) {
        __syncthreads();                                // smem/warp_loss reuse
        int s = grp * WARPS_PER_BLOCK + wid;
        float* hb_row = sm + wid * N_EMBED;

        // Load correlations -> h regs + shared hbar copy
        float4 h[4];
        {
            const float4* hb4 = (const float4*)(g_hbar + (size_t)s * N_EMBED);
            float4* dst = (float4*)hb_row;
            #pragma unroll
            for (int q = 0; q < 4; ++q) {
                float4 v = hb4[q * 32 + lane];
                h[q] = v;
                dst[q * 32 + lane] = v;
            }
        }
        __syncwarp();
        float* hf = (float*)h;

        unsigned used = 0;
        int   sup[K_SPARSE];
        float hbs[K_SPARSE];
        float Lm[K_SPARSE][K_SPARSE];
        float coef[K_SPARSE];

        #pragma unroll
        for (int k = 0; k < K_SPARSE; ++k) {
            // masked argmax of |h| (masked -> 0, first-max-index wins)
            float best = -1.f; int bidx = 0;
            #pragma unroll
            for (int q = 0; q < 4; ++q) {
                #pragma unroll
                for (int t = 0; t < 4; ++t) {
                    int li = q * 4 + t;                  // ascending gi order
                    float mv = ((used >> li) & 1u) ? 0.0f : fabsf(hf[li]);
                    int gi = q * 128 + lane * 4 + t;
                    if (mv > best) { best = mv; bidx = gi; }
                }
            }
            unsigned M = redux_max_u32(__float_as_uint(best));
            unsigned cand = (__float_as_uint(best) == M) ? (unsigned)bidx : 0xffffffffu;
            int bi = (int)redux_min_u32(cand);

            sup[k] = bi;
            hbs[k] = hb_row[bi];                        // broadcast LDS
            if (((bi >> 2) & 31) == lane)
                used |= 1u << ((((unsigned)bi >> 7) << 2) | (bi & 3));

            // incremental Cholesky (scalar G reads, L2-hot)
            if (k == 0) {
                Lm[0][0] = 1.f;
            } else {
                float w[3]; float ss = 0.f;
                #pragma unroll
                for (int a = 0; a < k; ++a) {
                    float gv = g_G[sup[a] * N_EMBED + bi];
                    #pragma unroll
                    for (int c = 0; c < a; ++c) gv -= Lm[a][c] * w[c];
                    w[a] = gv / Lm[a][a];
                    ss += w[a] * w[a];
                }
                #pragma unroll
                for (int a = 0; a < k; ++a) Lm[k][a] = w[a];
                Lm[k][k] = sqrtf(fmaxf(1.f - ss, 1e-12f));
            }

            // solve L y = hbs ; L^T coef = y (size k+1)
            {
                float y[K_SPARSE];
                #pragma unroll
                for (int a = 0; a <= k; ++a) {
                    float v = hbs[a];
                    #pragma unroll
                    for (int c = 0; c < a; ++c) v -= Lm[a][c] * y[c];
                    y[a] = v / Lm[a][a];
                }
                #pragma unroll
                for (int a = k; a >= 0; --a) {
                    float v = y[a];
                    #pragma unroll
                    for (int c = a + 1; c <= k; ++c) v -= Lm[c][a] * coef[c];
                    coef[a] = v / Lm[a][a];
                }
            }

            // h = hbar - sum_{j<=k} coef[j]*G[sup[j],:]
            if (k < K_SPARSE - 1) {
                const float4* hb4 = (const float4*)hb_row;
                #pragma unroll
                for (int q = 0; q < 4; ++q) {
                    float4 acc = hb4[q * 32 + lane];
                    #pragma unroll
                    for (int j = 0; j < K_SPARSE - 1; ++j) {
                        if (j <= k) {
                            float4 gv = ((const float4*)(g_G + sup[j] * N_EMBED))[q * 32 + lane];
                            acc.x -= coef[j] * gv.x;
                            acc.y -= coef[j] * gv.y;
                            acc.z -= coef[j] * gv.z;
                            acc.w -= coef[j] * gv.w;
                        }
                    }
                    h[q] = acc;
                }
            }
        }

        // quantize coefficients to 33 bins on [-2, 2]
        float cq[K_SPARSE];
        int   bq[K_SPARSE];
        #pragma unroll
        for (int j = 0; j < K_SPARSE; ++j) {
            float c  = fminf(fmaxf(coef[j], -2.f), 2.f);
            int   bi = (int)rintf((c + 2.f) * 8.f);
            bi = min(max(bi, 0), N_BINS - 1);
            bq[j] = bi;
            cq[j] = -2.f + 0.125f * (float)bi;
        }

        // tokens + stash support/coeffs for the cooperative epilogue
        if (lane == 0) {
            float* tok = out + ZQ_ELEMS + 1 + (size_t)s * K_SPARSE;
            #pragma unroll
            for (int j = 0; j < K_SPARSE; ++j) {
                tok[j] = (float)(sup[j] * N_BINS + bq[j]);
                sh_sup[wid][j] = sup[j];
                sh_cq [wid][j] = cq[j];
            }
        }
        __syncthreads();

        // coalesced epilogue: 8 consecutive-hw signals, channel-major
        int s0  = grp * WARPS_PER_BLOCK;
        int b0  = s0 >> 10;
        int hw0 = s0 & 1023;
        float lsum = 0.f;
        #pragma unroll
        for (int r = 0; r < 2; ++r) {
            int e  = tid + r * 256;
            int c  = e >> 3;
            int sl = e & 7;
            float rec = 0.f;
            #pragma unroll
            for (int j = 0; j < K_SPARSE; ++j)
                rec = fmaf(sh_cq[sl][j], g_DnT[sh_sup[sl][j] * EMBED_DIM + c], rec);
            int off = ((b0 * EMBED_DIM + c) << 10) + hw0 + sl;
            float ze = z_e[off];
            float d  = rec - ze;
            out[off] = ze + d;                 // z_q_ste
            lsum += d * d;
        }
        #pragma unroll
        for (int off = 16; off; off >>= 1) lsum += __shfl_xor_sync(0xffffffffu, lsum, off);
        if (lane == 0) warp_loss[wid] = lsum;
        __syncthreads();
        if (tid == 0) {
            float t = 0.f;
            #pragma unroll
            for (int w = 0; w < WARPS_PER_BLOCK; ++w) t += warp_loss[w];
            g_part[grp] = t;
        }
    }
    grid_sync(nblocks);

    // ======== Phase 4: deterministic final loss reduction (block 0) ========
    if (blockIdx.x == 0) {
        float* red = sm;
        float acc = 0.f;
        #pragma unroll
        for (int i = 0; i < OMP_GROUPS / 256; ++i) acc += g_part[tid + i * 256];
        red[tid] = acc;
        __syncthreads();
        for (int o = 128; o > 0; o >>= 1) {
            if (tid < o) red[tid] += red[tid + o];
            __syncthreads();
        }
        if (tid == 0) {
            float mse = red[0] / (float)ZQ_ELEMS;
            out[ZQ_ELEMS] = mse + 0.25f * mse;   // dl_loss + COMMIT * e_loss
        }
    }
}

// ---------------------------------------------------------------------------
extern "C" void kernel_launch(void* const* d_in, const int* in_sizes, int n_in,
                              void* d_out, int out_size) {
    const float* z_e  = (const float*)d_in[0];
    const float* dict = (const float*)d_in[1];
    float* out = (float*)d_out;

    cudaFuncSetAttribute(k_mega, cudaFuncAttributeMaxDynamicSharedMemorySize,
                         SMEM_BYTES);

    // Size the grid so every block is resident (spin barrier safety).
    int dev = 0, nsm = 148, occ = 3;
    cudaGetDevice(&dev);
    cudaDeviceGetAttribute(&nsm, cudaDevAttrMultiProcessorCount, dev);
    cudaOccupancyMaxActiveBlocksPerMultiprocessor(&occ, k_mega, 256, SMEM_BYTES);
    if (occ < 1) occ = 1;
    int nblocks = nsm * occ;
    if (nblocks > OMP_GROUPS) nblocks = OMP_GROUPS;

    k_mega<<<nblocks, 256, SMEM_BYTES>>>(z_e, dict, out, nblocks);
}